// round 2
// baseline (speedup 1.0000x reference)
#include <cuda_runtime.h>
#include <cuda_bf16.h>
#include <math.h>

#define NMAX 10000
#define EMAX 320000
#define HEADS 4
#define HID 128
#define QKV 512  // HEADS*HID

// ---------------- device scratch (static, no allocation) ----------------
__device__ float  g_Q[NMAX * QKV];
__device__ float  g_K[NMAX * QKV];
__device__ float  g_V[NMAX * QKV];
__device__ float  g_S[NMAX * HID];
__device__ float  g_H[NMAX * HID];
__device__ float4 g_W4[EMAX];          // per-edge exp weights (4 heads)
__device__ float  g_InvS[NMAX * HEADS];
__device__ int    g_deg[NMAX];
__device__ int    g_off[NMAX + 1];
__device__ int    g_cur[NMAX];
__device__ int    g_srcs[EMAX];

// ---------------- CSR build ----------------
__global__ void zero_int_kernel(int* p, int n) {
    int i = blockIdx.x * blockDim.x + threadIdx.x;
    if (i < n) p[i] = 0;
}

__global__ void count_deg_kernel(const int* __restrict__ dst, int* __restrict__ deg, int e) {
    int i = blockIdx.x * blockDim.x + threadIdx.x;
    if (i < e) atomicAdd(&deg[dst[i]], 1);
}

// single-block exclusive scan over deg[0..n), writes off[] and cur[]
__global__ void scan_kernel(const int* __restrict__ deg, int* __restrict__ off,
                            int* __restrict__ cur, int n, int e) {
    __shared__ int part[1024];
    int t = threadIdx.x;
    int chunk = (n + 1023) / 1024;
    int lo = t * chunk;
    int hi = lo + chunk; if (hi > n) hi = n;
    int s = 0;
    for (int i = lo; i < hi; i++) s += deg[i];
    part[t] = s;
    __syncthreads();
    // inclusive Hillis-Steele scan
    for (int d = 1; d < 1024; d <<= 1) {
        int v = (t >= d) ? part[t - d] : 0;
        __syncthreads();
        part[t] += v;
        __syncthreads();
    }
    int run = part[t] - s;  // exclusive prefix for this thread's chunk
    for (int i = lo; i < hi; i++) {
        off[i] = run;
        cur[i] = run;
        run += deg[i];
    }
    if (t == 0) off[n] = e;
}

__global__ void scatter_kernel(const int* __restrict__ ei, int* __restrict__ cur,
                               int* __restrict__ srcs, int e) {
    int i = blockIdx.x * blockDim.x + threadIdx.x;
    if (i < e) {
        int s = ei[i];
        int d = ei[e + i];
        int p = atomicAdd(&cur[d], 1);
        srcs[p] = s;
    }
}

// ---------------- SGEMM: C[M,Nc] = A[M,K] @ W[K,Nc] + bias ----------------
// 64x64 tile, BK=16, 128 threads, 4x8 per thread.
#define BM 64
#define BN 64
#define BK 16
__global__ __launch_bounds__(128) void sgemm_bias_kernel(
    const float* __restrict__ A, const float* __restrict__ W,
    const float* __restrict__ bias, float* __restrict__ C,
    int M, int K, int Nc)
{
    __shared__ float As[BK][BM];
    __shared__ float Bs[BK][BN];
    int bm = blockIdx.y * BM;
    int bn = blockIdx.x * BN;
    int tid = threadIdx.x;
    int ty = tid >> 3;   // 0..15 -> 4 rows each
    int tx = tid & 7;    // 0..7  -> 8 cols each
    float acc[4][8];
#pragma unroll
    for (int i = 0; i < 4; i++)
#pragma unroll
        for (int j = 0; j < 8; j++) acc[i][j] = 0.f;

    for (int k0 = 0; k0 < K; k0 += BK) {
#pragma unroll
        for (int l = 0; l < 2; l++) {
            int idx = tid * 2 + l;            // 0..255
            // A tile: 64 rows x 4 float4
            int ar = idx >> 2, ac4 = idx & 3;
            int grow = bm + ar;
            float4 av = make_float4(0.f, 0.f, 0.f, 0.f);
            if (grow < M) av = *(const float4*)&A[(size_t)grow * K + k0 + ac4 * 4];
            As[ac4 * 4 + 0][ar] = av.x;
            As[ac4 * 4 + 1][ar] = av.y;
            As[ac4 * 4 + 2][ar] = av.z;
            As[ac4 * 4 + 3][ar] = av.w;
            // B tile: 16 rows x 16 float4
            int br = idx >> 4, bc4 = idx & 15;
            *(float4*)&Bs[br][bc4 * 4] =
                *(const float4*)&W[(size_t)(k0 + br) * Nc + bn + bc4 * 4];
        }
        __syncthreads();
#pragma unroll
        for (int kk = 0; kk < BK; kk++) {
            float a[4], b[8];
            float4 a4 = *(const float4*)&As[kk][ty * 4];
            a[0] = a4.x; a[1] = a4.y; a[2] = a4.z; a[3] = a4.w;
            float4 b0 = *(const float4*)&Bs[kk][tx * 8];
            float4 b1 = *(const float4*)&Bs[kk][tx * 8 + 4];
            b[0] = b0.x; b[1] = b0.y; b[2] = b0.z; b[3] = b0.w;
            b[4] = b1.x; b[5] = b1.y; b[6] = b1.z; b[7] = b1.w;
#pragma unroll
            for (int i = 0; i < 4; i++)
#pragma unroll
                for (int j = 0; j < 8; j++) acc[i][j] += a[i] * b[j];
        }
        __syncthreads();
    }

#pragma unroll
    for (int i = 0; i < 4; i++) {
        int row = bm + ty * 4 + i;
        if (row >= M) continue;
#pragma unroll
        for (int j = 0; j < 8; j += 4) {
            int col = bn + tx * 8 + j;
            float4 v;
            v.x = acc[i][j + 0] + bias[col + 0];
            v.y = acc[i][j + 1] + bias[col + 1];
            v.z = acc[i][j + 2] + bias[col + 2];
            v.w = acc[i][j + 3] + bias[col + 3];
            *(float4*)&C[(size_t)row * Nc + col] = v;
        }
    }
}

// ---------------- attention pass 1: logits, segment softmax stats ----------------
// one block (128 threads = 4 warps) per destination node
__global__ __launch_bounds__(128) void attn_pass1_kernel(
    const float* __restrict__ Q, const float* __restrict__ K,
    const int* __restrict__ off, const int* __restrict__ srcs,
    float4* __restrict__ Wbuf, float* __restrict__ InvS)
{
    int node = blockIdx.x;
    int tid = threadIdx.x;
    int lane = tid & 31;
    int w = tid >> 5;

    __shared__ float4 qs[128];       // q[node] * 1/sqrt(HID), as float4
    __shared__ float wmax[4][4];
    __shared__ float wsum[4][4];
    __shared__ float m_s[4];

    const float scale = 0.08838834764831845f;  // 1/sqrt(128)
    const float4* qg = (const float4*)(Q + (size_t)node * QKV);
    float4 qv = qg[tid];
    qv.x *= scale; qv.y *= scale; qv.z *= scale; qv.w *= scale;
    qs[tid] = qv;
    __syncthreads();

    int start = off[node], end = off[node + 1];

    float lmax[4] = {-1e30f, -1e30f, -1e30f, -1e30f};
    for (int j = start + w; j < end; j += 4) {
        int s = srcs[j];
        const float4* kg = (const float4*)(K + (size_t)s * QKV);
        float d[4];
#pragma unroll
        for (int h = 0; h < 4; h++) {
            float4 kv = kg[h * 32 + lane];
            float4 qh = qs[h * 32 + lane];
            float dot = kv.x * qh.x + kv.y * qh.y + kv.z * qh.z + kv.w * qh.w;
#pragma unroll
            for (int o = 16; o > 0; o >>= 1) dot += __shfl_xor_sync(0xFFFFFFFFu, dot, o);
            d[h] = dot;
            lmax[h] = fmaxf(lmax[h], dot);
        }
        if (lane == 0) Wbuf[j] = make_float4(d[0], d[1], d[2], d[3]);
    }
    if (lane == 0) {
        wmax[w][0] = lmax[0]; wmax[w][1] = lmax[1];
        wmax[w][2] = lmax[2]; wmax[w][3] = lmax[3];
    }
    __syncthreads();
    if (tid < 4) {
        float m = fmaxf(fmaxf(wmax[0][tid], wmax[1][tid]),
                        fmaxf(wmax[2][tid], wmax[3][tid]));
        m_s[tid] = m;
    }
    __syncthreads();
    float m0 = m_s[0], m1 = m_s[1], m2 = m_s[2], m3 = m_s[3];

    float p0 = 0.f, p1 = 0.f, p2 = 0.f, p3 = 0.f;
    for (int j = start + tid; j < end; j += 128) {
        float4 a = Wbuf[j];
        a.x = __expf(a.x - m0);
        a.y = __expf(a.y - m1);
        a.z = __expf(a.z - m2);
        a.w = __expf(a.w - m3);
        Wbuf[j] = a;
        p0 += a.x; p1 += a.y; p2 += a.z; p3 += a.w;
    }
#pragma unroll
    for (int o = 16; o > 0; o >>= 1) {
        p0 += __shfl_xor_sync(0xFFFFFFFFu, p0, o);
        p1 += __shfl_xor_sync(0xFFFFFFFFu, p1, o);
        p2 += __shfl_xor_sync(0xFFFFFFFFu, p2, o);
        p3 += __shfl_xor_sync(0xFFFFFFFFu, p3, o);
    }
    if (lane == 0) {
        wsum[w][0] = p0; wsum[w][1] = p1; wsum[w][2] = p2; wsum[w][3] = p3;
    }
    __syncthreads();
    if (tid < 4) {
        float s = wsum[0][tid] + wsum[1][tid] + wsum[2][tid] + wsum[3][tid];
        InvS[node * HEADS + tid] = 0.25f / (s + 1e-16f);  // fold head-mean in
    }
}

// ---------------- attention pass 2: weighted V sum + skip + relu ----------------
__global__ __launch_bounds__(128) void attn_pass2_kernel(
    const float* __restrict__ V, const float4* __restrict__ Wbuf,
    const float* __restrict__ InvS, const float* __restrict__ S,
    const int* __restrict__ off, const int* __restrict__ srcs,
    float* __restrict__ Out)
{
    int node = blockIdx.x;
    int tid = threadIdx.x;
    int head = tid >> 5;
    __shared__ float sm[512];

    int start = off[node], end = off[node + 1];

    float4 acc = make_float4(0.f, 0.f, 0.f, 0.f);
    for (int j = start; j < end; j++) {
        float4 w4 = Wbuf[j];
        float wgt = (head == 0) ? w4.x : (head == 1) ? w4.y : (head == 2) ? w4.z : w4.w;
        int s = srcs[j];
        float4 v = ((const float4*)(V + (size_t)s * QKV))[tid];
        acc.x += wgt * v.x;
        acc.y += wgt * v.y;
        acc.z += wgt * v.z;
        acc.w += wgt * v.w;
    }
    float inv = InvS[node * HEADS + head];
    acc.x *= inv; acc.y *= inv; acc.z *= inv; acc.w *= inv;
    *(float4*)&sm[tid * 4] = acc;
    __syncthreads();

    if (tid < 32) {
#pragma unroll
        for (int i = 0; i < 4; i++) {
            int c = tid * 4 + i;
            float s = sm[c] + sm[128 + c] + sm[256 + c] + sm[384 + c]
                    + S[(size_t)node * HID + c];
            Out[(size_t)node * HID + c] = fmaxf(s, 0.f);
        }
    }
}

// ---------------- launch ----------------
extern "C" void kernel_launch(void* const* d_in, const int* in_sizes, int n_in,
                              void* d_out, int out_size) {
    const float* x   = (const float*)d_in[0];
    const int*   ei  = (const int*)d_in[1];      // int32 (JAX x64 disabled)
    const float* Wq0 = (const float*)d_in[3],  *bq0 = (const float*)d_in[4];
    const float* Wk0 = (const float*)d_in[5],  *bk0 = (const float*)d_in[6];
    const float* Wv0 = (const float*)d_in[7],  *bv0 = (const float*)d_in[8];
    const float* Ws0 = (const float*)d_in[9],  *bs0 = (const float*)d_in[10];
    const float* Wq1 = (const float*)d_in[11], *bq1 = (const float*)d_in[12];
    const float* Wk1 = (const float*)d_in[13], *bk1 = (const float*)d_in[14];
    const float* Wv1 = (const float*)d_in[15], *bv1 = (const float*)d_in[16];
    const float* Ws1 = (const float*)d_in[17], *bs1 = (const float*)d_in[18];
    float* out = (float*)d_out;

    int n = in_sizes[0] / 256;
    int e = in_sizes[1] / 2;

    float *Q, *K, *V, *S, *H, *InvS;
    float4* W4;
    int *deg, *off, *cur, *srcs;
    cudaGetSymbolAddress((void**)&Q,    g_Q);
    cudaGetSymbolAddress((void**)&K,    g_K);
    cudaGetSymbolAddress((void**)&V,    g_V);
    cudaGetSymbolAddress((void**)&S,    g_S);
    cudaGetSymbolAddress((void**)&H,    g_H);
    cudaGetSymbolAddress((void**)&InvS, g_InvS);
    cudaGetSymbolAddress((void**)&W4,   g_W4);
    cudaGetSymbolAddress((void**)&deg,  g_deg);
    cudaGetSymbolAddress((void**)&off,  g_off);
    cudaGetSymbolAddress((void**)&cur,  g_cur);
    cudaGetSymbolAddress((void**)&srcs, g_srcs);

    int tb = 256;
    // ---- CSR build (shared by both layers) ----
    zero_int_kernel<<<(n + tb - 1) / tb, tb>>>(deg, n);
    count_deg_kernel<<<(e + tb - 1) / tb, tb>>>(ei + e, deg, e);
    scan_kernel<<<1, 1024>>>(deg, off, cur, n, e);
    scatter_kernel<<<(e + tb - 1) / tb, tb>>>(ei, cur, srcs, e);

    // ---- layer 0 (d_in = 256) ----
    {
        dim3 g512((QKV + BN - 1) / BN, (n + BM - 1) / BM);
        dim3 g128((HID + BN - 1) / BN, (n + BM - 1) / BM);
        sgemm_bias_kernel<<<g512, 128>>>(x, Wq0, bq0, Q, n, 256, QKV);
        sgemm_bias_kernel<<<g512, 128>>>(x, Wk0, bk0, K, n, 256, QKV);
        sgemm_bias_kernel<<<g512, 128>>>(x, Wv0, bv0, V, n, 256, QKV);
        sgemm_bias_kernel<<<g128, 128>>>(x, Ws0, bs0, S, n, 256, HID);
        attn_pass1_kernel<<<n, 128>>>(Q, K, off, srcs, W4, InvS);
        attn_pass2_kernel<<<n, 128>>>(V, W4, InvS, S, off, srcs, H);
    }
    // ---- layer 1 (d_in = 128) ----
    {
        dim3 g512((QKV + BN - 1) / BN, (n + BM - 1) / BM);
        dim3 g128((HID + BN - 1) / BN, (n + BM - 1) / BM);
        sgemm_bias_kernel<<<g512, 128>>>(H, Wq1, bq1, Q, n, 128, QKV);
        sgemm_bias_kernel<<<g512, 128>>>(H, Wk1, bk1, K, n, 128, QKV);
        sgemm_bias_kernel<<<g512, 128>>>(H, Wv1, bv1, V, n, 128, QKV);
        sgemm_bias_kernel<<<g128, 128>>>(H, Ws1, bs1, S, n, 128, HID);
        attn_pass1_kernel<<<n, 128>>>(Q, K, off, srcs, W4, InvS);
        attn_pass2_kernel<<<n, 128>>>(V, W4, InvS, S, off, srcs, out);
    }
}

// round 3
// speedup vs baseline: 1.3365x; 1.3365x over previous
#include <cuda_runtime.h>
#include <cuda_bf16.h>
#include <math.h>

#define NMAX 10000
#define EMAX 320000
#define HEADS 4
#define HID 128
#define QKV 512  // HEADS*HID

// ---------------- device scratch (static, no allocation) ----------------
__device__ float  g_Q[NMAX * QKV];
__device__ float  g_K[NMAX * QKV];
__device__ float  g_V[NMAX * QKV];
__device__ float  g_S[NMAX * HID];
__device__ float  g_H[NMAX * HID];
__device__ float4 g_W4[EMAX];          // per-edge exp weights (4 heads)
__device__ float  g_InvS[NMAX * HEADS];
__device__ int    g_deg[NMAX];
__device__ int    g_off[NMAX + 1];
__device__ int    g_cur[NMAX];
__device__ int    g_srcs[EMAX];

// ---------------- CSR build ----------------
__global__ void zero_int_kernel(int* p, int n) {
    int i = blockIdx.x * blockDim.x + threadIdx.x;
    if (i < n) p[i] = 0;
}

__global__ void count_deg_kernel(const int* __restrict__ dst, int* __restrict__ deg, int e) {
    int i = blockIdx.x * blockDim.x + threadIdx.x;
    if (i < e) atomicAdd(&deg[dst[i]], 1);
}

// single-block exclusive scan over deg[0..n), writes off[] and cur[]
__global__ void scan_kernel(const int* __restrict__ deg, int* __restrict__ off,
                            int* __restrict__ cur, int n, int e) {
    __shared__ int part[1024];
    int t = threadIdx.x;
    int chunk = (n + 1023) / 1024;
    int lo = t * chunk;
    int hi = lo + chunk; if (hi > n) hi = n;
    int s = 0;
    for (int i = lo; i < hi; i++) s += deg[i];
    part[t] = s;
    __syncthreads();
    for (int d = 1; d < 1024; d <<= 1) {
        int v = (t >= d) ? part[t - d] : 0;
        __syncthreads();
        part[t] += v;
        __syncthreads();
    }
    int run = part[t] - s;
    for (int i = lo; i < hi; i++) {
        off[i] = run;
        cur[i] = run;
        run += deg[i];
    }
    if (t == 0) off[n] = e;
}

__global__ void scatter_kernel(const int* __restrict__ ei, int* __restrict__ cur,
                               int* __restrict__ srcs, int e) {
    int i = blockIdx.x * blockDim.x + threadIdx.x;
    if (i < e) {
        int s = ei[i];
        int d = ei[e + i];
        int p = atomicAdd(&cur[d], 1);
        srcs[p] = s;
    }
}

// ---------------- SGEMM v2: 128x64 tile, BK=16, 256 threads, 8x4 micro ----------
// C[M,Nc] = A[M,K] @ W[K,Nc] + bias.  blockIdx.z selects (W,bias,C) triple so
// Q/K/V run as one launch. Double-buffered smem, register-staged loads.
#define BM2 128
#define BN2 64
#define BK2 16

__global__ __launch_bounds__(256) void sgemm2_kernel(
    const float* __restrict__ A,
    const float* __restrict__ W0, const float* __restrict__ W1, const float* __restrict__ W2,
    const float* __restrict__ b0, const float* __restrict__ b1, const float* __restrict__ b2,
    float* __restrict__ C0, float* __restrict__ C1, float* __restrict__ C2,
    int M, int K, int Nc)
{
    const float* W    = (blockIdx.z == 0) ? W0 : (blockIdx.z == 1) ? W1 : W2;
    const float* bias = (blockIdx.z == 0) ? b0 : (blockIdx.z == 1) ? b1 : b2;
    float*       C    = (blockIdx.z == 0) ? C0 : (blockIdx.z == 1) ? C1 : C2;

    __shared__ float As[2][BK2][BM2];   // transposed: As[k][m]
    __shared__ float Bs[2][BK2][BN2];   // Bs[k][n]

    const int bm  = blockIdx.y * BM2;
    const int bn  = blockIdx.x * BN2;
    const int tid = threadIdx.x;
    const int tx  = tid & 15;   // N groups: 16 * 4 = 64
    const int ty  = tid >> 4;   // M groups: 16 * 8 = 128

    // A-tile load mapping: 512 float4 slots; thread t owns slots 2t, 2t+1.
    const int ar0 = (tid * 2) >> 2,     ac0 = (tid * 2) & 3;
    const int ar1 = (tid * 2 + 1) >> 2, ac1 = (tid * 2 + 1) & 3;
    // B-tile load mapping: 256 float4 slots; thread t owns slot t.
    const int br = tid >> 4, bc = tid & 15;

    float acc[8][4];
#pragma unroll
    for (int i = 0; i < 8; i++)
#pragma unroll
        for (int j = 0; j < 4; j++) acc[i][j] = 0.f;

    float4 aR0, aR1, bR;

    // prologue: load tile k0=0
    {
        const int g0 = bm + ar0, g1 = bm + ar1;
        aR0 = (g0 < M) ? *(const float4*)&A[(size_t)g0 * K + ac0 * 4]
                       : make_float4(0.f, 0.f, 0.f, 0.f);
        aR1 = (g1 < M) ? *(const float4*)&A[(size_t)g1 * K + ac1 * 4]
                       : make_float4(0.f, 0.f, 0.f, 0.f);
        bR = *(const float4*)&W[(size_t)br * Nc + bn + bc * 4];
        As[0][ac0 * 4 + 0][ar0] = aR0.x; As[0][ac0 * 4 + 1][ar0] = aR0.y;
        As[0][ac0 * 4 + 2][ar0] = aR0.z; As[0][ac0 * 4 + 3][ar0] = aR0.w;
        As[0][ac1 * 4 + 0][ar1] = aR1.x; As[0][ac1 * 4 + 1][ar1] = aR1.y;
        As[0][ac1 * 4 + 2][ar1] = aR1.z; As[0][ac1 * 4 + 3][ar1] = aR1.w;
        *(float4*)&Bs[0][br][bc * 4] = bR;
    }
    __syncthreads();

    int buf = 0;
    for (int k0 = BK2; k0 <= K; k0 += BK2) {
        const bool more = (k0 < K);
        if (more) {
            const int g0 = bm + ar0, g1 = bm + ar1;
            aR0 = (g0 < M) ? *(const float4*)&A[(size_t)g0 * K + k0 + ac0 * 4]
                           : make_float4(0.f, 0.f, 0.f, 0.f);
            aR1 = (g1 < M) ? *(const float4*)&A[(size_t)g1 * K + k0 + ac1 * 4]
                           : make_float4(0.f, 0.f, 0.f, 0.f);
            bR = *(const float4*)&W[(size_t)(k0 + br) * Nc + bn + bc * 4];
        }
#pragma unroll
        for (int kk = 0; kk < BK2; kk++) {
            float4 a0 = *(const float4*)&As[buf][kk][ty * 8];
            float4 a1 = *(const float4*)&As[buf][kk][ty * 8 + 4];
            float4 bv = *(const float4*)&Bs[buf][kk][tx * 4];
            float a[8] = {a0.x, a0.y, a0.z, a0.w, a1.x, a1.y, a1.z, a1.w};
            float b[4] = {bv.x, bv.y, bv.z, bv.w};
#pragma unroll
            for (int i = 0; i < 8; i++)
#pragma unroll
                for (int j = 0; j < 4; j++) acc[i][j] += a[i] * b[j];
        }
        if (more) {
            const int nb = buf ^ 1;
            As[nb][ac0 * 4 + 0][ar0] = aR0.x; As[nb][ac0 * 4 + 1][ar0] = aR0.y;
            As[nb][ac0 * 4 + 2][ar0] = aR0.z; As[nb][ac0 * 4 + 3][ar0] = aR0.w;
            As[nb][ac1 * 4 + 0][ar1] = aR1.x; As[nb][ac1 * 4 + 1][ar1] = aR1.y;
            As[nb][ac1 * 4 + 2][ar1] = aR1.z; As[nb][ac1 * 4 + 3][ar1] = aR1.w;
            *(float4*)&Bs[nb][br][bc * 4] = bR;
            __syncthreads();
            buf = nb;
        }
    }

    // epilogue: bias + store
    float4 bias4 = *(const float4*)&bias[bn + tx * 4];
#pragma unroll
    for (int i = 0; i < 8; i++) {
        int row = bm + ty * 8 + i;
        if (row >= M) continue;
        float4 v;
        v.x = acc[i][0] + bias4.x;
        v.y = acc[i][1] + bias4.y;
        v.z = acc[i][2] + bias4.z;
        v.w = acc[i][3] + bias4.w;
        *(float4*)&C[(size_t)row * Nc + bn + tx * 4] = v;
    }
}

// ---------------- attention pass 1: logits, segment softmax stats ----------------
__global__ __launch_bounds__(128) void attn_pass1_kernel(
    const float* __restrict__ Q, const float* __restrict__ K,
    const int* __restrict__ off, const int* __restrict__ srcs,
    float4* __restrict__ Wbuf, float* __restrict__ InvS)
{
    int node = blockIdx.x;
    int tid = threadIdx.x;
    int lane = tid & 31;
    int w = tid >> 5;

    __shared__ float4 qs[128];
    __shared__ float wmax[4][4];
    __shared__ float wsum[4][4];
    __shared__ float m_s[4];

    const float scale = 0.08838834764831845f;  // 1/sqrt(128)
    const float4* qg = (const float4*)(Q + (size_t)node * QKV);
    float4 qv = qg[tid];
    qv.x *= scale; qv.y *= scale; qv.z *= scale; qv.w *= scale;
    qs[tid] = qv;
    __syncthreads();

    int start = off[node], end = off[node + 1];

    float lmax[4] = {-1e30f, -1e30f, -1e30f, -1e30f};
    for (int j = start + w; j < end; j += 4) {
        int s = srcs[j];
        const float4* kg = (const float4*)(K + (size_t)s * QKV);
        float d[4];
#pragma unroll
        for (int h = 0; h < 4; h++) {
            float4 kv = kg[h * 32 + lane];
            float4 qh = qs[h * 32 + lane];
            float dot = kv.x * qh.x + kv.y * qh.y + kv.z * qh.z + kv.w * qh.w;
#pragma unroll
            for (int o = 16; o > 0; o >>= 1) dot += __shfl_xor_sync(0xFFFFFFFFu, dot, o);
            d[h] = dot;
            lmax[h] = fmaxf(lmax[h], dot);
        }
        if (lane == 0) Wbuf[j] = make_float4(d[0], d[1], d[2], d[3]);
    }
    if (lane == 0) {
        wmax[w][0] = lmax[0]; wmax[w][1] = lmax[1];
        wmax[w][2] = lmax[2]; wmax[w][3] = lmax[3];
    }
    __syncthreads();
    if (tid < 4) {
        float m = fmaxf(fmaxf(wmax[0][tid], wmax[1][tid]),
                        fmaxf(wmax[2][tid], wmax[3][tid]));
        m_s[tid] = m;
    }
    __syncthreads();
    float m0 = m_s[0], m1 = m_s[1], m2 = m_s[2], m3 = m_s[3];

    float p0 = 0.f, p1 = 0.f, p2 = 0.f, p3 = 0.f;
    for (int j = start + tid; j < end; j += 128) {
        float4 a = Wbuf[j];
        a.x = __expf(a.x - m0);
        a.y = __expf(a.y - m1);
        a.z = __expf(a.z - m2);
        a.w = __expf(a.w - m3);
        Wbuf[j] = a;
        p0 += a.x; p1 += a.y; p2 += a.z; p3 += a.w;
    }
#pragma unroll
    for (int o = 16; o > 0; o >>= 1) {
        p0 += __shfl_xor_sync(0xFFFFFFFFu, p0, o);
        p1 += __shfl_xor_sync(0xFFFFFFFFu, p1, o);
        p2 += __shfl_xor_sync(0xFFFFFFFFu, p2, o);
        p3 += __shfl_xor_sync(0xFFFFFFFFu, p3, o);
    }
    if (lane == 0) {
        wsum[w][0] = p0; wsum[w][1] = p1; wsum[w][2] = p2; wsum[w][3] = p3;
    }
    __syncthreads();
    if (tid < 4) {
        float s = wsum[0][tid] + wsum[1][tid] + wsum[2][tid] + wsum[3][tid];
        InvS[node * HEADS + tid] = 0.25f / (s + 1e-16f);
    }
}

// ---------------- attention pass 2: weighted V sum + skip + relu ----------------
__global__ __launch_bounds__(128) void attn_pass2_kernel(
    const float* __restrict__ V, const float4* __restrict__ Wbuf,
    const float* __restrict__ InvS, const float* __restrict__ S,
    const int* __restrict__ off, const int* __restrict__ srcs,
    float* __restrict__ Out)
{
    int node = blockIdx.x;
    int tid = threadIdx.x;
    int head = tid >> 5;
    __shared__ float sm[512];

    int start = off[node], end = off[node + 1];

    float4 acc = make_float4(0.f, 0.f, 0.f, 0.f);
    for (int j = start; j < end; j++) {
        float4 w4 = Wbuf[j];
        float wgt = (head == 0) ? w4.x : (head == 1) ? w4.y : (head == 2) ? w4.z : w4.w;
        int s = srcs[j];
        float4 v = ((const float4*)(V + (size_t)s * QKV))[tid];
        acc.x += wgt * v.x;
        acc.y += wgt * v.y;
        acc.z += wgt * v.z;
        acc.w += wgt * v.w;
    }
    float inv = InvS[node * HEADS + head];
    acc.x *= inv; acc.y *= inv; acc.z *= inv; acc.w *= inv;
    *(float4*)&sm[tid * 4] = acc;
    __syncthreads();

    if (tid < 32) {
#pragma unroll
        for (int i = 0; i < 4; i++) {
            int c = tid * 4 + i;
            float s = sm[c] + sm[128 + c] + sm[256 + c] + sm[384 + c]
                    + S[(size_t)node * HID + c];
            Out[(size_t)node * HID + c] = fmaxf(s, 0.f);
        }
    }
}

// ---------------- launch ----------------
extern "C" void kernel_launch(void* const* d_in, const int* in_sizes, int n_in,
                              void* d_out, int out_size) {
    const float* x   = (const float*)d_in[0];
    const int*   ei  = (const int*)d_in[1];
    const float* Wq0 = (const float*)d_in[3],  *bq0 = (const float*)d_in[4];
    const float* Wk0 = (const float*)d_in[5],  *bk0 = (const float*)d_in[6];
    const float* Wv0 = (const float*)d_in[7],  *bv0 = (const float*)d_in[8];
    const float* Ws0 = (const float*)d_in[9],  *bs0 = (const float*)d_in[10];
    const float* Wq1 = (const float*)d_in[11], *bq1 = (const float*)d_in[12];
    const float* Wk1 = (const float*)d_in[13], *bk1 = (const float*)d_in[14];
    const float* Wv1 = (const float*)d_in[15], *bv1 = (const float*)d_in[16];
    const float* Ws1 = (const float*)d_in[17], *bs1 = (const float*)d_in[18];
    float* out = (float*)d_out;

    int n = in_sizes[0] / 256;
    int e = in_sizes[1] / 2;

    float *Q, *K, *V, *S, *H, *InvS;
    float4* W4;
    int *deg, *off, *cur, *srcs;
    cudaGetSymbolAddress((void**)&Q,    g_Q);
    cudaGetSymbolAddress((void**)&K,    g_K);
    cudaGetSymbolAddress((void**)&V,    g_V);
    cudaGetSymbolAddress((void**)&S,    g_S);
    cudaGetSymbolAddress((void**)&H,    g_H);
    cudaGetSymbolAddress((void**)&InvS, g_InvS);
    cudaGetSymbolAddress((void**)&W4,   g_W4);
    cudaGetSymbolAddress((void**)&deg,  g_deg);
    cudaGetSymbolAddress((void**)&off,  g_off);
    cudaGetSymbolAddress((void**)&cur,  g_cur);
    cudaGetSymbolAddress((void**)&srcs, g_srcs);

    int tb = 256;
    // ---- CSR build ----
    zero_int_kernel<<<(n + tb - 1) / tb, tb>>>(deg, n);
    count_deg_kernel<<<(e + tb - 1) / tb, tb>>>(ei + e, deg, e);
    scan_kernel<<<1, 1024>>>(deg, off, cur, n, e);
    scatter_kernel<<<(e + tb - 1) / tb, tb>>>(ei, cur, srcs, e);

    const int gy = (n + BM2 - 1) / BM2;

    // ---- layer 0 (d_in = 256) ----
    {
        dim3 gqkv(QKV / BN2, gy, 3);
        dim3 gs(HID / BN2, gy, 1);
        sgemm2_kernel<<<gqkv, 256>>>(x, Wq0, Wk0, Wv0, bq0, bk0, bv0,
                                     Q, K, V, n, 256, QKV);
        sgemm2_kernel<<<gs, 256>>>(x, Ws0, Ws0, Ws0, bs0, bs0, bs0,
                                   S, S, S, n, 256, HID);
        attn_pass1_kernel<<<n, 128>>>(Q, K, off, srcs, W4, InvS);
        attn_pass2_kernel<<<n, 128>>>(V, W4, InvS, S, off, srcs, H);
    }
    // ---- layer 1 (d_in = 128) ----
    {
        dim3 gqkv(QKV / BN2, gy, 3);
        dim3 gs(HID / BN2, gy, 1);
        sgemm2_kernel<<<gqkv, 256>>>(H, Wq1, Wk1, Wv1, bq1, bk1, bv1,
                                     Q, K, V, n, 128, QKV);
        sgemm2_kernel<<<gs, 256>>>(H, Ws1, Ws1, Ws1, bs1, bs1, bs1,
                                   S, S, S, n, 128, HID);
        attn_pass1_kernel<<<n, 128>>>(Q, K, off, srcs, W4, InvS);
        attn_pass2_kernel<<<n, 128>>>(V, W4, InvS, S, off, srcs, out);
    }
}

// round 5
// speedup vs baseline: 1.7602x; 1.3171x over previous
#include <cuda_runtime.h>
#include <cuda_bf16.h>
#include <math.h>
#include <stdint.h>

#define NMAX 10000
#define EMAX 320000
#define HEADS 4
#define HID 128
#define QKV 512  // HEADS*HID

// ---------------- device scratch (static, no allocation) ----------------
__device__ float  g_Q[NMAX * QKV];
__device__ float  g_K[NMAX * QKV];
__device__ float  g_V[NMAX * QKV];
__device__ float  g_S[NMAX * HID];
__device__ float  g_H[NMAX * HID];
__device__ float4 g_W4[EMAX];          // per-edge exp weights (4 heads)
__device__ float  g_InvS[NMAX * HEADS];
__device__ int    g_deg[NMAX];
__device__ int    g_off[NMAX + 1];
__device__ int    g_cur[NMAX];
__device__ int    g_srcs[EMAX];
__device__ float  g_Wt[638976];        // transposed weights [Nc, K] packed

// offsets (floats) into g_Wt
#define WT_Q0 0
#define WT_K0 131072
#define WT_V0 262144
#define WT_S0 393216
#define WT_Q1 425984
#define WT_K1 491520
#define WT_V1 557056
#define WT_S1 622592

// ---------------- CSR build ----------------
__global__ void zero_int_kernel(int* p, int n) {
    int i = blockIdx.x * blockDim.x + threadIdx.x;
    if (i < n) p[i] = 0;
}

__global__ void count_deg_kernel(const int* __restrict__ dst, int* __restrict__ deg, int e) {
    int i = blockIdx.x * blockDim.x + threadIdx.x;
    if (i < e) atomicAdd(&deg[dst[i]], 1);
}

__global__ void scan_kernel(const int* __restrict__ deg, int* __restrict__ off,
                            int* __restrict__ cur, int n, int e) {
    __shared__ int part[1024];
    int t = threadIdx.x;
    int chunk = (n + 1023) / 1024;
    int lo = t * chunk;
    int hi = lo + chunk; if (hi > n) hi = n;
    int s = 0;
    for (int i = lo; i < hi; i++) s += deg[i];
    part[t] = s;
    __syncthreads();
    for (int d = 1; d < 1024; d <<= 1) {
        int v = (t >= d) ? part[t - d] : 0;
        __syncthreads();
        part[t] += v;
        __syncthreads();
    }
    int run = part[t] - s;
    for (int i = lo; i < hi; i++) {
        off[i] = run;
        cur[i] = run;
        run += deg[i];
    }
    if (t == 0) off[n] = e;
}

__global__ void scatter_kernel(const int* __restrict__ ei, int* __restrict__ cur,
                               int* __restrict__ srcs, int e) {
    int i = blockIdx.x * blockDim.x + threadIdx.x;
    if (i < e) {
        int s = ei[i];
        int d = ei[e + i];
        int p = atomicAdd(&cur[d], 1);
        srcs[p] = s;
    }
}

// ---------------- weight transpose: Wt[n][k] = W[k][n] ----------------
__global__ void transpose_kernel(const float* __restrict__ W, float* __restrict__ Wt,
                                 int K, int Nc) {
    __shared__ float t[32][33];
    int x = blockIdx.x * 32 + threadIdx.x;  // Nc dim
    int y = blockIdx.y * 32 + threadIdx.y;  // K dim
#pragma unroll
    for (int i = 0; i < 32; i += 8)
        if (y + i < K && x < Nc) t[threadIdx.y + i][threadIdx.x] = W[(size_t)(y + i) * Nc + x];
    __syncthreads();
    x = blockIdx.y * 32 + threadIdx.x;  // K
    y = blockIdx.x * 32 + threadIdx.y;  // Nc
#pragma unroll
    for (int i = 0; i < 32; i += 8)
        if (y + i < Nc && x < K) Wt[(size_t)(y + i) * K + x] = t[threadIdx.x][threadIdx.y + i];
}

// ---------------- tf32 mma.sync GEMM ----------------
// C[M,Nc] = A[M,K] @ Wt[Nc,K]^T + bias.  Block tile 128x128, BK=16, 256 threads.
// 8 warps: 2 (M) x 4 (N); warp tile 64x32 = 4x4 mma m16n8k8 tiles, 2 k-steps.
#define TM 128
#define TN 128
#define TBK 16
#define SSTRIDE 20   // padded smem row stride (words) -> conflict-free frags

__device__ __forceinline__ uint32_t f2tf32(float f) {
    uint32_t r;
    asm("cvt.rna.tf32.f32 %0, %1;" : "=r"(r) : "f"(f));
    return r;
}

__device__ __forceinline__ void mma_tf32(float c[4], const uint32_t a[4],
                                         const uint32_t b[2]) {
    asm volatile(
        "mma.sync.aligned.m16n8k8.row.col.f32.tf32.tf32.f32 "
        "{%0,%1,%2,%3}, {%4,%5,%6,%7}, {%8,%9}, {%0,%1,%2,%3};"
        : "+f"(c[0]), "+f"(c[1]), "+f"(c[2]), "+f"(c[3])
        : "r"(a[0]), "r"(a[1]), "r"(a[2]), "r"(a[3]), "r"(b[0]), "r"(b[1]));
}

__global__ __launch_bounds__(256) void tf32_gemm_kernel(
    const float* __restrict__ A,
    const float* __restrict__ Wt0, const float* __restrict__ Wt1, const float* __restrict__ Wt2,
    const float* __restrict__ b0_, const float* __restrict__ b1_, const float* __restrict__ b2_,
    float* __restrict__ C0, float* __restrict__ C1, float* __restrict__ C2,
    int M, int K, int Nc)
{
    const float* Wt   = (blockIdx.z == 0) ? Wt0 : (blockIdx.z == 1) ? Wt1 : Wt2;
    const float* bias = (blockIdx.z == 0) ? b0_ : (blockIdx.z == 1) ? b1_ : b2_;
    float*       C    = (blockIdx.z == 0) ? C0  : (blockIdx.z == 1) ? C1  : C2;

    __shared__ uint32_t sA[TM * SSTRIDE];
    __shared__ uint32_t sB[TN * SSTRIDE];

    const int tid  = threadIdx.x;
    const int wid  = tid >> 5;
    const int lane = tid & 31;
    const int bm = blockIdx.y * TM;
    const int bn = blockIdx.x * TN;

    const int warp_m = wid >> 2;          // 0..1
    const int warp_n = wid & 3;           // 0..3
    const int m0w = warp_m * 64;
    const int n0w = warp_n * 32;
    const int grp = lane >> 2;            // 0..7
    const int tig = lane & 3;             // 0..3

    float acc[4][4][4];
#pragma unroll
    for (int mt = 0; mt < 4; mt++)
#pragma unroll
        for (int nt = 0; nt < 4; nt++)
#pragma unroll
            for (int i = 0; i < 4; i++) acc[mt][nt][i] = 0.f;

    const int ktiles = K / TBK;
    for (int kt = 0; kt < ktiles; kt++) {
        const int k0 = kt * TBK;
        // load tiles: 512 float4 slots each, 2 per thread
#pragma unroll
        for (int l = 0; l < 2; l++) {
            int idx = tid * 2 + l;
            int r = idx >> 2, c4 = idx & 3;
            int row = bm + r; if (row >= M) row = M - 1;
            float4 va = *(const float4*)&A[(size_t)row * K + k0 + c4 * 4];
            uint4 ta = make_uint4(f2tf32(va.x), f2tf32(va.y), f2tf32(va.z), f2tf32(va.w));
            *(uint4*)&sA[r * SSTRIDE + c4 * 4] = ta;
            float4 vb = *(const float4*)&Wt[(size_t)(bn + r) * K + k0 + c4 * 4];
            uint4 tb = make_uint4(f2tf32(vb.x), f2tf32(vb.y), f2tf32(vb.z), f2tf32(vb.w));
            *(uint4*)&sB[r * SSTRIDE + c4 * 4] = tb;
        }
        __syncthreads();

#pragma unroll
        for (int ks = 0; ks < 2; ks++) {
            uint32_t af[4][4], bf[4][2];
#pragma unroll
            for (int mt = 0; mt < 4; mt++) {
                int base = (m0w + mt * 16 + grp) * SSTRIDE + ks * 8 + tig;
                af[mt][0] = sA[base];
                af[mt][1] = sA[base + 8 * SSTRIDE];
                af[mt][2] = sA[base + 4];
                af[mt][3] = sA[base + 8 * SSTRIDE + 4];
            }
#pragma unroll
            for (int nt = 0; nt < 4; nt++) {
                int base = (n0w + nt * 8 + grp) * SSTRIDE + ks * 8 + tig;
                bf[nt][0] = sB[base];
                bf[nt][1] = sB[base + 4];
            }
#pragma unroll
            for (int mt = 0; mt < 4; mt++)
#pragma unroll
                for (int nt = 0; nt < 4; nt++)
                    mma_tf32(acc[mt][nt], af[mt], bf[nt]);
        }
        __syncthreads();
    }

    // epilogue: bias + store (float2 per c-pair)
#pragma unroll
    for (int mt = 0; mt < 4; mt++) {
        int r0 = bm + m0w + mt * 16 + grp;
        int r1 = r0 + 8;
#pragma unroll
        for (int nt = 0; nt < 4; nt++) {
            int col = bn + n0w + nt * 8 + 2 * tig;
            float2 bi = *(const float2*)&bias[col];
            if (r0 < M) {
                float2 v = make_float2(acc[mt][nt][0] + bi.x, acc[mt][nt][1] + bi.y);
                *(float2*)&C[(size_t)r0 * Nc + col] = v;
            }
            if (r1 < M) {
                float2 v = make_float2(acc[mt][nt][2] + bi.x, acc[mt][nt][3] + bi.y);
                *(float2*)&C[(size_t)r1 * Nc + col] = v;
            }
        }
    }
}

// ---------------- attention pass 1: logits, segment softmax stats ----------------
__global__ __launch_bounds__(128) void attn_pass1_kernel(
    const float* __restrict__ Q, const float* __restrict__ K,
    const int* __restrict__ off, const int* __restrict__ srcs,
    float4* __restrict__ Wbuf, float* __restrict__ InvS)
{
    int node = blockIdx.x;
    int tid = threadIdx.x;
    int lane = tid & 31;
    int w = tid >> 5;

    __shared__ float4 qs[128];
    __shared__ float wmax[4][4];
    __shared__ float wsum[4][4];
    __shared__ float m_s[4];

    const float scale = 0.08838834764831845f;  // 1/sqrt(128)
    const float4* qg = (const float4*)(Q + (size_t)node * QKV);
    float4 qv = qg[tid];
    qv.x *= scale; qv.y *= scale; qv.z *= scale; qv.w *= scale;
    qs[tid] = qv;
    __syncthreads();

    int start = off[node], end = off[node + 1];

    float lmax[4] = {-1e30f, -1e30f, -1e30f, -1e30f};
    for (int j = start + w; j < end; j += 4) {
        int s = srcs[j];
        const float4* kg = (const float4*)(K + (size_t)s * QKV);
        float d[4];
#pragma unroll
        for (int h = 0; h < 4; h++) {
            float4 kv = kg[h * 32 + lane];
            float4 qh = qs[h * 32 + lane];
            float dot = kv.x * qh.x + kv.y * qh.y + kv.z * qh.z + kv.w * qh.w;
#pragma unroll
            for (int o = 16; o > 0; o >>= 1) dot += __shfl_xor_sync(0xFFFFFFFFu, dot, o);
            d[h] = dot;
            lmax[h] = fmaxf(lmax[h], dot);
        }
        if (lane == 0) Wbuf[j] = make_float4(d[0], d[1], d[2], d[3]);
    }
    if (lane == 0) {
        wmax[w][0] = lmax[0]; wmax[w][1] = lmax[1];
        wmax[w][2] = lmax[2]; wmax[w][3] = lmax[3];
    }
    __syncthreads();
    if (tid < 4) {
        float m = fmaxf(fmaxf(wmax[0][tid], wmax[1][tid]),
                        fmaxf(wmax[2][tid], wmax[3][tid]));
        m_s[tid] = m;
    }
    __syncthreads();
    float m0 = m_s[0], m1 = m_s[1], m2 = m_s[2], m3 = m_s[3];

    float p0 = 0.f, p1 = 0.f, p2 = 0.f, p3 = 0.f;
    for (int j = start + tid; j < end; j += 128) {
        float4 a = Wbuf[j];
        a.x = __expf(a.x - m0);
        a.y = __expf(a.y - m1);
        a.z = __expf(a.z - m2);
        a.w = __expf(a.w - m3);
        Wbuf[j] = a;
        p0 += a.x; p1 += a.y; p2 += a.z; p3 += a.w;
    }
#pragma unroll
    for (int o = 16; o > 0; o >>= 1) {
        p0 += __shfl_xor_sync(0xFFFFFFFFu, p0, o);
        p1 += __shfl_xor_sync(0xFFFFFFFFu, p1, o);
        p2 += __shfl_xor_sync(0xFFFFFFFFu, p2, o);
        p3 += __shfl_xor_sync(0xFFFFFFFFu, p3, o);
    }
    if (lane == 0) {
        wsum[w][0] = p0; wsum[w][1] = p1; wsum[w][2] = p2; wsum[w][3] = p3;
    }
    __syncthreads();
    if (tid < 4) {
        float s = wsum[0][tid] + wsum[1][tid] + wsum[2][tid] + wsum[3][tid];
        InvS[node * HEADS + tid] = 0.25f / (s + 1e-16f);
    }
}

// ---------------- attention pass 2: weighted V sum + skip + relu ----------------
__global__ __launch_bounds__(128) void attn_pass2_kernel(
    const float* __restrict__ V, const float4* __restrict__ Wbuf,
    const float* __restrict__ InvS, const float* __restrict__ S,
    const int* __restrict__ off, const int* __restrict__ srcs,
    float* __restrict__ Out)
{
    int node = blockIdx.x;
    int tid = threadIdx.x;
    int head = tid >> 5;
    __shared__ float sm[512];

    int start = off[node], end = off[node + 1];

    float4 acc = make_float4(0.f, 0.f, 0.f, 0.f);
    for (int j = start; j < end; j++) {
        float4 w4 = Wbuf[j];
        float wgt = (head == 0) ? w4.x : (head == 1) ? w4.y : (head == 2) ? w4.z : w4.w;
        int s = srcs[j];
        float4 v = ((const float4*)(V + (size_t)s * QKV))[tid];
        acc.x += wgt * v.x;
        acc.y += wgt * v.y;
        acc.z += wgt * v.z;
        acc.w += wgt * v.w;
    }
    float inv = InvS[node * HEADS + head];
    acc.x *= inv; acc.y *= inv; acc.z *= inv; acc.w *= inv;
    *(float4*)&sm[tid * 4] = acc;
    __syncthreads();

    if (tid < 32) {
#pragma unroll
        for (int i = 0; i < 4; i++) {
            int c = tid * 4 + i;
            float s = sm[c] + sm[128 + c] + sm[256 + c] + sm[384 + c]
                    + S[(size_t)node * HID + c];
            Out[(size_t)node * HID + c] = fmaxf(s, 0.f);
        }
    }
}

// ---------------- launch ----------------
extern "C" void kernel_launch(void* const* d_in, const int* in_sizes, int n_in,
                              void* d_out, int out_size) {
    const float* x   = (const float*)d_in[0];
    const int*   ei  = (const int*)d_in[1];
    const float* Wq0 = (const float*)d_in[3],  *bq0 = (const float*)d_in[4];
    const float* Wk0 = (const float*)d_in[5],  *bk0 = (const float*)d_in[6];
    const float* Wv0 = (const float*)d_in[7],  *bv0 = (const float*)d_in[8];
    const float* Ws0 = (const float*)d_in[9],  *bs0 = (const float*)d_in[10];
    const float* Wq1 = (const float*)d_in[11], *bq1 = (const float*)d_in[12];
    const float* Wk1 = (const float*)d_in[13], *bk1 = (const float*)d_in[14];
    const float* Wv1 = (const float*)d_in[15], *bv1 = (const float*)d_in[16];
    const float* Ws1 = (const float*)d_in[17], *bs1 = (const float*)d_in[18];
    float* out = (float*)d_out;

    int n = in_sizes[0] / 256;
    int e = in_sizes[1] / 2;

    float *Q, *K, *V, *S, *H, *InvS, *Wt;
    float4* W4;
    int *deg, *off, *cur, *srcs;
    cudaGetSymbolAddress((void**)&Q,    g_Q);
    cudaGetSymbolAddress((void**)&K,    g_K);
    cudaGetSymbolAddress((void**)&V,    g_V);
    cudaGetSymbolAddress((void**)&S,    g_S);
    cudaGetSymbolAddress((void**)&H,    g_H);
    cudaGetSymbolAddress((void**)&InvS, g_InvS);
    cudaGetSymbolAddress((void**)&W4,   g_W4);
    cudaGetSymbolAddress((void**)&deg,  g_deg);
    cudaGetSymbolAddress((void**)&off,  g_off);
    cudaGetSymbolAddress((void**)&cur,  g_cur);
    cudaGetSymbolAddress((void**)&srcs, g_srcs);
    cudaGetSymbolAddress((void**)&Wt,   g_Wt);

    int tb = 256;
    // ---- CSR build ----
    zero_int_kernel<<<(n + tb - 1) / tb, tb>>>(deg, n);
    count_deg_kernel<<<(e + tb - 1) / tb, tb>>>(ei + e, deg, e);
    scan_kernel<<<1, 1024>>>(deg, off, cur, n, e);
    scatter_kernel<<<(e + tb - 1) / tb, tb>>>(ei, cur, srcs, e);

    // ---- weight transposes ----
    dim3 tpb(32, 8);
    {
        dim3 g0(QKV / 32, 256 / 32);
        dim3 gs0(HID / 32, 256 / 32);
        dim3 g1(QKV / 32, 128 / 32);
        dim3 gs1(HID / 32, 128 / 32);
        transpose_kernel<<<g0, tpb>>>(Wq0, Wt + WT_Q0, 256, QKV);
        transpose_kernel<<<g0, tpb>>>(Wk0, Wt + WT_K0, 256, QKV);
        transpose_kernel<<<g0, tpb>>>(Wv0, Wt + WT_V0, 256, QKV);
        transpose_kernel<<<gs0, tpb>>>(Ws0, Wt + WT_S0, 256, HID);
        transpose_kernel<<<g1, tpb>>>(Wq1, Wt + WT_Q1, 128, QKV);
        transpose_kernel<<<g1, tpb>>>(Wk1, Wt + WT_K1, 128, QKV);
        transpose_kernel<<<g1, tpb>>>(Wv1, Wt + WT_V1, 128, QKV);
        transpose_kernel<<<gs1, tpb>>>(Ws1, Wt + WT_S1, 128, HID);
    }

    const int gy = (n + TM - 1) / TM;

    // ---- layer 0 (d_in = 256) ----
    {
        dim3 gqkv(QKV / TN, gy, 3);
        dim3 gs(HID / TN, gy, 1);
        tf32_gemm_kernel<<<gqkv, 256>>>(x, Wt + WT_Q0, Wt + WT_K0, Wt + WT_V0,
                                        bq0, bk0, bv0, Q, K, V, n, 256, QKV);
        tf32_gemm_kernel<<<gs, 256>>>(x, Wt + WT_S0, Wt + WT_S0, Wt + WT_S0,
                                      bs0, bs0, bs0, S, S, S, n, 256, HID);
        attn_pass1_kernel<<<n, 128>>>(Q, K, off, srcs, W4, InvS);
        attn_pass2_kernel<<<n, 128>>>(V, W4, InvS, S, off, srcs, H);
    }
    // ---- layer 1 (d_in = 128) ----
    {
        dim3 gqkv(QKV / TN, gy, 3);
        dim3 gs(HID / TN, gy, 1);
        tf32_gemm_kernel<<<gqkv, 256>>>(H, Wt + WT_Q1, Wt + WT_K1, Wt + WT_V1,
                                        bq1, bk1, bv1, Q, K, V, n, 128, QKV);
        tf32_gemm_kernel<<<gs, 256>>>(H, Wt + WT_S1, Wt + WT_S1, Wt + WT_S1,
                                      bs1, bs1, bs1, S, S, S, n, 128, HID);
        attn_pass1_kernel<<<n, 128>>>(Q, K, off, srcs, W4, InvS);
        attn_pass2_kernel<<<n, 128>>>(V, W4, InvS, S, off, srcs, out);
    }
}

// round 6
// speedup vs baseline: 1.9429x; 1.1038x over previous
#include <cuda_runtime.h>
#include <cuda_bf16.h>
#include <math.h>
#include <stdint.h>

#define NMAX 10000
#define EMAX 320000
#define HEADS 4
#define HID 128
#define QKV 512  // HEADS*HID

// ---------------- device scratch (static, no allocation) ----------------
__device__ float  g_Q[NMAX * QKV];
__device__ float  g_K[NMAX * QKV];
__device__ float  g_V[NMAX * QKV];
__device__ __nv_bfloat16 g_Kh[NMAX * QKV];
__device__ __nv_bfloat16 g_Vh[NMAX * QKV];
__device__ float  g_S[NMAX * HID];
__device__ float  g_H[NMAX * HID];
__device__ float4 g_W4[EMAX];          // per-edge exp weights (4 heads)
__device__ float  g_InvS[NMAX * HEADS];
__device__ int    g_deg[NMAX];
__device__ int    g_off[NMAX + 1];
__device__ int    g_cur[NMAX];
__device__ int    g_srcs[EMAX];
__device__ float  g_Wt[638976];        // transposed weights [Nc, K] packed

#define WT_Q0 0
#define WT_K0 131072
#define WT_V0 262144
#define WT_S0 393216
#define WT_Q1 425984
#define WT_K1 491520
#define WT_V1 557056
#define WT_S1 622592

__device__ __forceinline__ float2 bf2f2(uint32_t u) {
    __nv_bfloat162 h = *reinterpret_cast<__nv_bfloat162*>(&u);
    return __bfloat1622float2(h);
}

// ---------------- CSR build ----------------
__global__ void zero_int_kernel(int* p, int n) {
    int i = blockIdx.x * blockDim.x + threadIdx.x;
    if (i < n) p[i] = 0;
}

__global__ void count_deg_kernel(const int* __restrict__ dst, int* __restrict__ deg, int e) {
    int i = blockIdx.x * blockDim.x + threadIdx.x;
    if (i < e) atomicAdd(&deg[dst[i]], 1);
}

__global__ void scan_kernel(const int* __restrict__ deg, int* __restrict__ off,
                            int* __restrict__ cur, int n, int e) {
    __shared__ int part[1024];
    int t = threadIdx.x;
    int chunk = (n + 1023) / 1024;
    int lo = t * chunk;
    int hi = lo + chunk; if (hi > n) hi = n;
    int s = 0;
    for (int i = lo; i < hi; i++) s += deg[i];
    part[t] = s;
    __syncthreads();
    for (int d = 1; d < 1024; d <<= 1) {
        int v = (t >= d) ? part[t - d] : 0;
        __syncthreads();
        part[t] += v;
        __syncthreads();
    }
    int run = part[t] - s;
    for (int i = lo; i < hi; i++) {
        off[i] = run;
        cur[i] = run;
        run += deg[i];
    }
    if (t == 0) off[n] = e;
}

__global__ void scatter_kernel(const int* __restrict__ ei, int* __restrict__ cur,
                               int* __restrict__ srcs, int e) {
    int i = blockIdx.x * blockDim.x + threadIdx.x;
    if (i < e) {
        int s = ei[i];
        int d = ei[e + i];
        int p = atomicAdd(&cur[d], 1);
        srcs[p] = s;
    }
}

// ---------------- weight transpose: Wt[n][k] = W[k][n] ----------------
__global__ void transpose_kernel(const float* __restrict__ W, float* __restrict__ Wt,
                                 int K, int Nc) {
    __shared__ float t[32][33];
    int x = blockIdx.x * 32 + threadIdx.x;
    int y = blockIdx.y * 32 + threadIdx.y;
#pragma unroll
    for (int i = 0; i < 32; i += 8)
        if (y + i < K && x < Nc) t[threadIdx.y + i][threadIdx.x] = W[(size_t)(y + i) * Nc + x];
    __syncthreads();
    x = blockIdx.y * 32 + threadIdx.x;
    y = blockIdx.x * 32 + threadIdx.y;
#pragma unroll
    for (int i = 0; i < 32; i += 8)
        if (y + i < Nc && x < K) Wt[(size_t)(y + i) * K + x] = t[threadIdx.x][threadIdx.y + i];
}

// ---------------- fp32 -> bf16 convert ----------------
__global__ void cvt_bf16_kernel(const float4* __restrict__ src, uint2* __restrict__ dst, int n4) {
    int i = blockIdx.x * blockDim.x + threadIdx.x;
    if (i < n4) {
        float4 v = src[i];
        __nv_bfloat162 lo = __floats2bfloat162_rn(v.x, v.y);
        __nv_bfloat162 hi = __floats2bfloat162_rn(v.z, v.w);
        uint2 o;
        o.x = *reinterpret_cast<uint32_t*>(&lo);
        o.y = *reinterpret_cast<uint32_t*>(&hi);
        dst[i] = o;
    }
}

// ---------------- tf32 mma.sync GEMM ----------------
#define TM 128
#define TN 128
#define TBK 16
#define SSTRIDE 20

__device__ __forceinline__ uint32_t f2tf32(float f) {
    uint32_t r;
    asm("cvt.rna.tf32.f32 %0, %1;" : "=r"(r) : "f"(f));
    return r;
}

__device__ __forceinline__ void mma_tf32(float c[4], const uint32_t a[4],
                                         const uint32_t b[2]) {
    asm volatile(
        "mma.sync.aligned.m16n8k8.row.col.f32.tf32.tf32.f32 "
        "{%0,%1,%2,%3}, {%4,%5,%6,%7}, {%8,%9}, {%0,%1,%2,%3};"
        : "+f"(c[0]), "+f"(c[1]), "+f"(c[2]), "+f"(c[3])
        : "r"(a[0]), "r"(a[1]), "r"(a[2]), "r"(a[3]), "r"(b[0]), "r"(b[1]));
}

__global__ __launch_bounds__(256) void tf32_gemm_kernel(
    const float* __restrict__ A,
    const float* __restrict__ Wt0, const float* __restrict__ Wt1, const float* __restrict__ Wt2,
    const float* __restrict__ b0_, const float* __restrict__ b1_, const float* __restrict__ b2_,
    float* __restrict__ C0, float* __restrict__ C1, float* __restrict__ C2,
    int M, int K, int Nc)
{
    const float* Wt   = (blockIdx.z == 0) ? Wt0 : (blockIdx.z == 1) ? Wt1 : Wt2;
    const float* bias = (blockIdx.z == 0) ? b0_ : (blockIdx.z == 1) ? b1_ : b2_;
    float*       C    = (blockIdx.z == 0) ? C0  : (blockIdx.z == 1) ? C1  : C2;

    __shared__ uint32_t sA[TM * SSTRIDE];
    __shared__ uint32_t sB[TN * SSTRIDE];

    const int tid  = threadIdx.x;
    const int wid  = tid >> 5;
    const int lane = tid & 31;
    const int bm = blockIdx.y * TM;
    const int bn = blockIdx.x * TN;

    const int warp_m = wid >> 2;
    const int warp_n = wid & 3;
    const int m0w = warp_m * 64;
    const int n0w = warp_n * 32;
    const int grp = lane >> 2;
    const int tig = lane & 3;

    float acc[4][4][4];
#pragma unroll
    for (int mt = 0; mt < 4; mt++)
#pragma unroll
        for (int nt = 0; nt < 4; nt++)
#pragma unroll
            for (int i = 0; i < 4; i++) acc[mt][nt][i] = 0.f;

    const int ktiles = K / TBK;
    for (int kt = 0; kt < ktiles; kt++) {
        const int k0 = kt * TBK;
#pragma unroll
        for (int l = 0; l < 2; l++) {
            int idx = tid * 2 + l;
            int r = idx >> 2, c4 = idx & 3;
            int row = bm + r; if (row >= M) row = M - 1;
            float4 va = *(const float4*)&A[(size_t)row * K + k0 + c4 * 4];
            uint4 ta = make_uint4(f2tf32(va.x), f2tf32(va.y), f2tf32(va.z), f2tf32(va.w));
            *(uint4*)&sA[r * SSTRIDE + c4 * 4] = ta;
            float4 vb = *(const float4*)&Wt[(size_t)(bn + r) * K + k0 + c4 * 4];
            uint4 tb = make_uint4(f2tf32(vb.x), f2tf32(vb.y), f2tf32(vb.z), f2tf32(vb.w));
            *(uint4*)&sB[r * SSTRIDE + c4 * 4] = tb;
        }
        __syncthreads();

#pragma unroll
        for (int ks = 0; ks < 2; ks++) {
            uint32_t af[4][4], bf[4][2];
#pragma unroll
            for (int mt = 0; mt < 4; mt++) {
                int base = (m0w + mt * 16 + grp) * SSTRIDE + ks * 8 + tig;
                af[mt][0] = sA[base];
                af[mt][1] = sA[base + 8 * SSTRIDE];
                af[mt][2] = sA[base + 4];
                af[mt][3] = sA[base + 8 * SSTRIDE + 4];
            }
#pragma unroll
            for (int nt = 0; nt < 4; nt++) {
                int base = (n0w + nt * 8 + grp) * SSTRIDE + ks * 8 + tig;
                bf[nt][0] = sB[base];
                bf[nt][1] = sB[base + 4];
            }
#pragma unroll
            for (int mt = 0; mt < 4; mt++)
#pragma unroll
                for (int nt = 0; nt < 4; nt++)
                    mma_tf32(acc[mt][nt], af[mt], bf[nt]);
        }
        __syncthreads();
    }

#pragma unroll
    for (int mt = 0; mt < 4; mt++) {
        int r0 = bm + m0w + mt * 16 + grp;
        int r1 = r0 + 8;
#pragma unroll
        for (int nt = 0; nt < 4; nt++) {
            int col = bn + n0w + nt * 8 + 2 * tig;
            float2 bi = *(const float2*)&bias[col];
            if (r0 < M) {
                float2 v = make_float2(acc[mt][nt][0] + bi.x, acc[mt][nt][1] + bi.y);
                *(float2*)&C[(size_t)r0 * Nc + col] = v;
            }
            if (r1 < M) {
                float2 v = make_float2(acc[mt][nt][2] + bi.x, acc[mt][nt][3] + bi.y);
                *(float2*)&C[(size_t)r1 * Nc + col] = v;
            }
        }
    }
}

// ---------------- attention pass 1: logits (bf16 K), segment softmax stats ----
__global__ __launch_bounds__(128) void attn_pass1_kernel(
    const float* __restrict__ Q, const __nv_bfloat16* __restrict__ Kh,
    const int* __restrict__ off, const int* __restrict__ srcs,
    float4* __restrict__ Wbuf, float* __restrict__ InvS)
{
    int node = blockIdx.x;
    int tid = threadIdx.x;
    int lane = tid & 31;
    int w = tid >> 5;

    __shared__ float wmax[4][4];
    __shared__ float wsum[4][4];
    __shared__ float m_s[4];

    const float scale = 0.08838834764831845f;  // 1/sqrt(128)
    // q in registers: lane owns elements [lane*16, lane*16+16)
    float qreg[16];
    {
        const float4* qg = (const float4*)(Q + (size_t)node * QKV);
#pragma unroll
        for (int c = 0; c < 4; c++) {
            float4 v = qg[lane * 4 + c];
            qreg[c * 4 + 0] = v.x * scale;
            qreg[c * 4 + 1] = v.y * scale;
            qreg[c * 4 + 2] = v.z * scale;
            qreg[c * 4 + 3] = v.w * scale;
        }
    }

    int start = off[node], end = off[node + 1];

    float lmax[4] = {-1e30f, -1e30f, -1e30f, -1e30f};
    for (int j = start + w; j < end; j += 4) {
        int s = srcs[j];
        const uint4* kg = (const uint4*)(Kh + (size_t)s * QKV);
        uint4 k0 = kg[lane * 2];
        uint4 k1 = kg[lane * 2 + 1];
        float part = 0.f;
        {
            float2 a;
            a = bf2f2(k0.x); part += qreg[0] * a.x + qreg[1] * a.y;
            a = bf2f2(k0.y); part += qreg[2] * a.x + qreg[3] * a.y;
            a = bf2f2(k0.z); part += qreg[4] * a.x + qreg[5] * a.y;
            a = bf2f2(k0.w); part += qreg[6] * a.x + qreg[7] * a.y;
            a = bf2f2(k1.x); part += qreg[8] * a.x + qreg[9] * a.y;
            a = bf2f2(k1.y); part += qreg[10] * a.x + qreg[11] * a.y;
            a = bf2f2(k1.z); part += qreg[12] * a.x + qreg[13] * a.y;
            a = bf2f2(k1.w); part += qreg[14] * a.x + qreg[15] * a.y;
        }
        // reduce within 8-lane head groups
        part += __shfl_xor_sync(0xFFFFFFFFu, part, 1);
        part += __shfl_xor_sync(0xFFFFFFFFu, part, 2);
        part += __shfl_xor_sync(0xFFFFFFFFu, part, 4);
        float d0 = __shfl_sync(0xFFFFFFFFu, part, 0);
        float d1 = __shfl_sync(0xFFFFFFFFu, part, 8);
        float d2 = __shfl_sync(0xFFFFFFFFu, part, 16);
        float d3 = __shfl_sync(0xFFFFFFFFu, part, 24);
        if (lane == 0) {
            Wbuf[j] = make_float4(d0, d1, d2, d3);
            lmax[0] = fmaxf(lmax[0], d0);
            lmax[1] = fmaxf(lmax[1], d1);
            lmax[2] = fmaxf(lmax[2], d2);
            lmax[3] = fmaxf(lmax[3], d3);
        }
    }
    if (lane == 0) {
        wmax[w][0] = lmax[0]; wmax[w][1] = lmax[1];
        wmax[w][2] = lmax[2]; wmax[w][3] = lmax[3];
    }
    __syncthreads();
    if (tid < 4) {
        float m = fmaxf(fmaxf(wmax[0][tid], wmax[1][tid]),
                        fmaxf(wmax[2][tid], wmax[3][tid]));
        m_s[tid] = m;
    }
    __syncthreads();
    float m0 = m_s[0], m1 = m_s[1], m2 = m_s[2], m3 = m_s[3];

    float p0 = 0.f, p1 = 0.f, p2 = 0.f, p3 = 0.f;
    for (int j = start + tid; j < end; j += 128) {
        float4 a = Wbuf[j];
        a.x = __expf(a.x - m0);
        a.y = __expf(a.y - m1);
        a.z = __expf(a.z - m2);
        a.w = __expf(a.w - m3);
        Wbuf[j] = a;
        p0 += a.x; p1 += a.y; p2 += a.z; p3 += a.w;
    }
#pragma unroll
    for (int o = 16; o > 0; o >>= 1) {
        p0 += __shfl_xor_sync(0xFFFFFFFFu, p0, o);
        p1 += __shfl_xor_sync(0xFFFFFFFFu, p1, o);
        p2 += __shfl_xor_sync(0xFFFFFFFFu, p2, o);
        p3 += __shfl_xor_sync(0xFFFFFFFFu, p3, o);
    }
    if (lane == 0) {
        wsum[w][0] = p0; wsum[w][1] = p1; wsum[w][2] = p2; wsum[w][3] = p3;
    }
    __syncthreads();
    if (tid < 4) {
        float s = wsum[0][tid] + wsum[1][tid] + wsum[2][tid] + wsum[3][tid];
        InvS[node * HEADS + tid] = 0.25f / (s + 1e-16f);
    }
}

// ---------------- attention pass 2: weighted V sum (bf16 V) + skip + relu ----
__global__ __launch_bounds__(128) void attn_pass2_kernel(
    const __nv_bfloat16* __restrict__ Vh, const float4* __restrict__ Wbuf,
    const float* __restrict__ InvS, const float* __restrict__ S,
    const int* __restrict__ off, const int* __restrict__ srcs,
    float* __restrict__ Out)
{
    int node = blockIdx.x;
    int tid = threadIdx.x;
    int head = tid >> 5;
    __shared__ float sm[512];

    int start = off[node], end = off[node + 1];

    float4 acc = make_float4(0.f, 0.f, 0.f, 0.f);
    int j = start;
    for (; j + 1 < end; j += 2) {
        int s0 = srcs[j], s1 = srcs[j + 1];
        uint2 u0 = ((const uint2*)(Vh + (size_t)s0 * QKV))[tid];
        uint2 u1 = ((const uint2*)(Vh + (size_t)s1 * QKV))[tid];
        float4 w0 = Wbuf[j], w1 = Wbuf[j + 1];
        float g0 = (head == 0) ? w0.x : (head == 1) ? w0.y : (head == 2) ? w0.z : w0.w;
        float g1 = (head == 0) ? w1.x : (head == 1) ? w1.y : (head == 2) ? w1.z : w1.w;
        float2 a0 = bf2f2(u0.x), b0 = bf2f2(u0.y);
        float2 a1 = bf2f2(u1.x), b1 = bf2f2(u1.y);
        acc.x += g0 * a0.x + g1 * a1.x;
        acc.y += g0 * a0.y + g1 * a1.y;
        acc.z += g0 * b0.x + g1 * b1.x;
        acc.w += g0 * b0.y + g1 * b1.y;
    }
    if (j < end) {
        int s0 = srcs[j];
        uint2 u0 = ((const uint2*)(Vh + (size_t)s0 * QKV))[tid];
        float4 w0 = Wbuf[j];
        float g0 = (head == 0) ? w0.x : (head == 1) ? w0.y : (head == 2) ? w0.z : w0.w;
        float2 a0 = bf2f2(u0.x), b0 = bf2f2(u0.y);
        acc.x += g0 * a0.x;
        acc.y += g0 * a0.y;
        acc.z += g0 * b0.x;
        acc.w += g0 * b0.y;
    }
    float inv = InvS[node * HEADS + head];
    acc.x *= inv; acc.y *= inv; acc.z *= inv; acc.w *= inv;
    *(float4*)&sm[tid * 4] = acc;
    __syncthreads();

    if (tid < 32) {
#pragma unroll
        for (int i = 0; i < 4; i++) {
            int c = tid * 4 + i;
            float s = sm[c] + sm[128 + c] + sm[256 + c] + sm[384 + c]
                    + S[(size_t)node * HID + c];
            Out[(size_t)node * HID + c] = fmaxf(s, 0.f);
        }
    }
}

// ---------------- launch ----------------
extern "C" void kernel_launch(void* const* d_in, const int* in_sizes, int n_in,
                              void* d_out, int out_size) {
    const float* x   = (const float*)d_in[0];
    const int*   ei  = (const int*)d_in[1];
    const float* Wq0 = (const float*)d_in[3],  *bq0 = (const float*)d_in[4];
    const float* Wk0 = (const float*)d_in[5],  *bk0 = (const float*)d_in[6];
    const float* Wv0 = (const float*)d_in[7],  *bv0 = (const float*)d_in[8];
    const float* Ws0 = (const float*)d_in[9],  *bs0 = (const float*)d_in[10];
    const float* Wq1 = (const float*)d_in[11], *bq1 = (const float*)d_in[12];
    const float* Wk1 = (const float*)d_in[13], *bk1 = (const float*)d_in[14];
    const float* Wv1 = (const float*)d_in[15], *bv1 = (const float*)d_in[16];
    const float* Ws1 = (const float*)d_in[17], *bs1 = (const float*)d_in[18];
    float* out = (float*)d_out;

    int n = in_sizes[0] / 256;
    int e = in_sizes[1] / 2;

    float *Q, *K, *V, *S, *H, *InvS, *Wt;
    __nv_bfloat16 *Kh, *Vh;
    float4* W4;
    int *deg, *off, *cur, *srcs;
    cudaGetSymbolAddress((void**)&Q,    g_Q);
    cudaGetSymbolAddress((void**)&K,    g_K);
    cudaGetSymbolAddress((void**)&V,    g_V);
    cudaGetSymbolAddress((void**)&Kh,   g_Kh);
    cudaGetSymbolAddress((void**)&Vh,   g_Vh);
    cudaGetSymbolAddress((void**)&S,    g_S);
    cudaGetSymbolAddress((void**)&H,    g_H);
    cudaGetSymbolAddress((void**)&InvS, g_InvS);
    cudaGetSymbolAddress((void**)&W4,   g_W4);
    cudaGetSymbolAddress((void**)&deg,  g_deg);
    cudaGetSymbolAddress((void**)&off,  g_off);
    cudaGetSymbolAddress((void**)&cur,  g_cur);
    cudaGetSymbolAddress((void**)&srcs, g_srcs);
    cudaGetSymbolAddress((void**)&Wt,   g_Wt);

    int tb = 256;
    // ---- CSR build ----
    zero_int_kernel<<<(n + tb - 1) / tb, tb>>>(deg, n);
    count_deg_kernel<<<(e + tb - 1) / tb, tb>>>(ei + e, deg, e);
    scan_kernel<<<1, 1024>>>(deg, off, cur, n, e);
    scatter_kernel<<<(e + tb - 1) / tb, tb>>>(ei, cur, srcs, e);

    // ---- weight transposes ----
    dim3 tpb(32, 8);
    {
        dim3 g0(QKV / 32, 256 / 32);
        dim3 gs0(HID / 32, 256 / 32);
        dim3 g1(QKV / 32, 128 / 32);
        dim3 gs1(HID / 32, 128 / 32);
        transpose_kernel<<<g0, tpb>>>(Wq0, Wt + WT_Q0, 256, QKV);
        transpose_kernel<<<g0, tpb>>>(Wk0, Wt + WT_K0, 256, QKV);
        transpose_kernel<<<g0, tpb>>>(Wv0, Wt + WT_V0, 256, QKV);
        transpose_kernel<<<gs0, tpb>>>(Ws0, Wt + WT_S0, 256, HID);
        transpose_kernel<<<g1, tpb>>>(Wq1, Wt + WT_Q1, 128, QKV);
        transpose_kernel<<<g1, tpb>>>(Wk1, Wt + WT_K1, 128, QKV);
        transpose_kernel<<<g1, tpb>>>(Wv1, Wt + WT_V1, 128, QKV);
        transpose_kernel<<<gs1, tpb>>>(Ws1, Wt + WT_S1, 128, HID);
    }

    const int gy = (n + TM - 1) / TM;
    const int n4 = n * QKV / 4;
    const int cvtg = (n4 + 255) / 256;

    // ---- layer 0 (d_in = 256) ----
    {
        dim3 gqkv(QKV / TN, gy, 3);
        dim3 gs(HID / TN, gy, 1);
        tf32_gemm_kernel<<<gqkv, 256>>>(x, Wt + WT_Q0, Wt + WT_K0, Wt + WT_V0,
                                        bq0, bk0, bv0, Q, K, V, n, 256, QKV);
        tf32_gemm_kernel<<<gs, 256>>>(x, Wt + WT_S0, Wt + WT_S0, Wt + WT_S0,
                                      bs0, bs0, bs0, S, S, S, n, 256, HID);
        cvt_bf16_kernel<<<cvtg, 256>>>((const float4*)K, (uint2*)Kh, n4);
        cvt_bf16_kernel<<<cvtg, 256>>>((const float4*)V, (uint2*)Vh, n4);
        attn_pass1_kernel<<<n, 128>>>(Q, Kh, off, srcs, W4, InvS);
        attn_pass2_kernel<<<n, 128>>>(Vh, W4, InvS, S, off, srcs, H);
    }
    // ---- layer 1 (d_in = 128) ----
    {
        dim3 gqkv(QKV / TN, gy, 3);
        dim3 gs(HID / TN, gy, 1);
        tf32_gemm_kernel<<<gqkv, 256>>>(H, Wt + WT_Q1, Wt + WT_K1, Wt + WT_V1,
                                        bq1, bk1, bv1, Q, K, V, n, 128, QKV);
        tf32_gemm_kernel<<<gs, 256>>>(H, Wt + WT_S1, Wt + WT_S1, Wt + WT_S1,
                                      bs1, bs1, bs1, S, S, S, n, 128, HID);
        cvt_bf16_kernel<<<cvtg, 256>>>((const float4*)K, (uint2*)Kh, n4);
        cvt_bf16_kernel<<<cvtg, 256>>>((const float4*)V, (uint2*)Vh, n4);
        attn_pass1_kernel<<<n, 128>>>(Q, Kh, off, srcs, W4, InvS);
        attn_pass2_kernel<<<n, 128>>>(Vh, W4, InvS, S, off, srcs, out);
    }
}